// round 8
// baseline (speedup 1.0000x reference)
#include <cuda_runtime.h>

// DynamicUpsamplingFilter: out[b,c,h,w] = sum_{dy,dx} x_pad[b,c,h+dy,w+dx] * filters[b,dy*3+dx,h,w]
// x: [4,128,180,320] f32, filters: [4,9,180,320] f32, out: [4,128,180,320] f32.
//
// R8 = R7 (4w x 2h tile, 16 ch/thread, batched loads; 53.3us) with the
// channel loop unrolled x4 and a 255-reg budget (128 threads, 2 blocks/SM).
// 48 independent loads in flight per warp per iteration (~per-warp LDG
// ceiling), peak live regs ~185 -> no spill. Warps/SM 12->8 but
// outstanding loads/SM +33% and each iteration carries ~580 cyc of FMA
// work to cover other warps' latency.

constexpr int B = 4, C = 128, H = 180, W = 320;
constexpr int HW = H * W;
constexpr int WQ = W / 4;            // 80 pixel-quads per row
constexpr int HP = H / 2;            // 90 row-pairs
constexpr int CCH = 16;              // channels per thread
constexpr int NCQ = C / CCH;         // 8 channel-groups
constexpr int THREADS = 128;
constexpr int NTHREADS_TOTAL = B * NCQ * HP * WQ;  // 230400
constexpr int GRID = NTHREADS_TOTAL / THREADS;     // 1800
constexpr int UNROLL = 4;

__global__ __launch_bounds__(THREADS, 2)
void duf_kernel(const float* __restrict__ x,
                const float* __restrict__ f,
                float* __restrict__ out)
{
    int idx = blockIdx.x * THREADS + threadIdx.x;

    // consecutive threads -> consecutive wq for coalescing
    int wq = idx % WQ;
    int t  = idx / WQ;
    int hp = t % HP;
    t /= HP;
    int cq = t % NCQ;
    int b  = t / NCQ;
    int w  = wq * 4;
    int h  = hp * 2;                 // output rows h, h+1

    // ---- filter taps for both output rows (pixels w..w+3) ----
    const float* fp0 = f + (size_t)b * 9 * HW + (size_t)h * W + w;
    float4 fv0[9], fv1[9];
#pragma unroll
    for (int i = 0; i < 9; ++i) {
        fv0[i] = *(const float4*)(fp0 + (size_t)i * HW);        // row h
        fv1[i] = *(const float4*)(fp0 + (size_t)i * HW + W);    // row h+1
    }

    // vertical boundaries
    if (hp == 0) {
#pragma unroll
        for (int i = 0; i < 3; ++i) fv0[i] = make_float4(0.f, 0.f, 0.f, 0.f);
    }
    if (hp == HP - 1) {
#pragma unroll
        for (int i = 6; i < 9; ++i) fv1[i] = make_float4(0.f, 0.f, 0.f, 0.f);
    }
    // horizontal boundaries
    if (w == 0) {
        fv0[0].x = 0.f; fv0[3].x = 0.f; fv0[6].x = 0.f;
        fv1[0].x = 0.f; fv1[3].x = 0.f; fv1[6].x = 0.f;
    }
    if (w == W - 4) {
        fv0[2].w = 0.f; fv0[5].w = 0.f; fv0[8].w = 0.f;
        fv1[2].w = 0.f; fv1[5].w = 0.f; fv1[8].w = 0.f;
    }

    // input rows h-1 .. h+2, clamped (dead loads in-bounds, filter zeroed)
    int roff[4];
    roff[0] = (hp > 0)      ? -W    : 0;     // row h-1
    roff[1] = 0;                              // row h
    roff[2] = W;                              // row h+1
    roff[3] = (hp < HP - 1) ? 2 * W : W;     // row h+2
    int offm1 = (w > 0)     ? -1 : 0;        // column w-1
    int offp4 = (w + 4 < W) ?  4 : 3;        // column w+4

    const float* xp = x   + ((size_t)b * C + cq * CCH) * HW + (size_t)h * W + w;
    float*       op = out + ((size_t)b * C + cq * CCH) * HW + (size_t)h * W + w;

    for (int c = 0; c < CCH; c += UNROLL) {
        // ---- issue ALL loads for UNROLL channels up front (48 independent) ----
        float4 m[UNROLL][4];
        float  vm[UNROLL][4], vp[UNROLL][4];
#pragma unroll
        for (int u = 0; u < UNROLL; ++u) {
            const float* xc = xp + (size_t)(c + u) * HW;
#pragma unroll
            for (int r = 0; r < 4; ++r) {
                const float* row = xc + roff[r];
                m[u][r]  = *(const float4*)row;   // columns w..w+3
                vm[u][r] = __ldg(row + offm1);    // column w-1
                vp[u][r] = __ldg(row + offp4);    // column w+4
            }
        }

#pragma unroll
        for (int u = 0; u < UNROLL; ++u) {
            // output row h: input rows 0,1,2
            float a0 = 0.f, a1 = 0.f, a2 = 0.f, a3 = 0.f;
#pragma unroll
            for (int j = 0; j < 3; ++j) {
                float4 F0 = fv0[3 * j + 0], F1 = fv0[3 * j + 1], F2 = fv0[3 * j + 2];
                float4 mm = m[u][j]; float vml = vm[u][j], vpr = vp[u][j];
                a0 = fmaf(vml,  F0.x, a0); a0 = fmaf(mm.x, F1.x, a0); a0 = fmaf(mm.y, F2.x, a0);
                a1 = fmaf(mm.x, F0.y, a1); a1 = fmaf(mm.y, F1.y, a1); a1 = fmaf(mm.z, F2.y, a1);
                a2 = fmaf(mm.y, F0.z, a2); a2 = fmaf(mm.z, F1.z, a2); a2 = fmaf(mm.w, F2.z, a2);
                a3 = fmaf(mm.z, F0.w, a3); a3 = fmaf(mm.w, F1.w, a3); a3 = fmaf(vpr,  F2.w, a3);
            }
            // output row h+1: input rows 1,2,3
            float b0 = 0.f, b1 = 0.f, b2 = 0.f, b3 = 0.f;
#pragma unroll
            for (int j = 0; j < 3; ++j) {
                float4 F0 = fv1[3 * j + 0], F1 = fv1[3 * j + 1], F2 = fv1[3 * j + 2];
                float4 mm = m[u][j + 1]; float vml = vm[u][j + 1], vpr = vp[u][j + 1];
                b0 = fmaf(vml,  F0.x, b0); b0 = fmaf(mm.x, F1.x, b0); b0 = fmaf(mm.y, F2.x, b0);
                b1 = fmaf(mm.x, F0.y, b1); b1 = fmaf(mm.y, F1.y, b1); b1 = fmaf(mm.z, F2.y, b1);
                b2 = fmaf(mm.y, F0.z, b2); b2 = fmaf(mm.z, F1.z, b2); b2 = fmaf(mm.w, F2.z, b2);
                b3 = fmaf(mm.z, F0.w, b3); b3 = fmaf(mm.w, F1.w, b3); b3 = fmaf(vpr,  F2.w, b3);
            }

            float* oc = op + (size_t)(c + u) * HW;
            *(float4*)oc       = make_float4(a0, a1, a2, a3);
            *(float4*)(oc + W) = make_float4(b0, b1, b2, b3);
        }
    }
}

extern "C" void kernel_launch(void* const* d_in, const int* in_sizes, int n_in,
                              void* d_out, int out_size)
{
    const float* x = (const float*)d_in[0];   // [4,128,180,320]
    const float* f = (const float*)d_in[1];   // [4,9,180,320]
    float* out = (float*)d_out;               // [4,128,180,320]

    duf_kernel<<<GRID, THREADS>>>(x, f, out);
}

// round 9
// speedup vs baseline: 1.0812x; 1.0812x over previous
#include <cuda_runtime.h>

// DynamicUpsamplingFilter: out[b,c,h,w] = sum_{dy,dx} x_pad[b,c,h+dy,w+dx] * filters[b,dy*3+dx,h,w]
// x: [4,128,180,320] f32, filters: [4,9,180,320] f32, out: [4,128,180,320] f32.
//
// R9 = R7 structure (4w x 2h tile, 16 ch/thread, 12 warps/SM) + software
// pipelining: double-buffered channel loads, batch c+1 issued BEFORE the
// FMAs of batch c, so the scoreboard wait lands one iteration after issue
// instead of inside the same iteration (R7/R8's phase bubble = ~400 cyc
// exposed latency per iteration). Regs ~140 -> fits launch_bounds(128,3).

constexpr int B = 4, C = 128, H = 180, W = 320;
constexpr int HW = H * W;
constexpr int WQ = W / 4;            // 80 pixel-quads per row
constexpr int HP = H / 2;            // 90 row-pairs
constexpr int CCH = 16;              // channels per thread
constexpr int NCQ = C / CCH;         // 8 channel-groups
constexpr int THREADS = 128;
constexpr int NTHREADS_TOTAL = B * NCQ * HP * WQ;  // 230400
constexpr int GRID = NTHREADS_TOTAL / THREADS;     // 1800

struct Buf {
    float4 m[4];
    float  vm[4], vp[4];
};

__device__ __forceinline__ void load_ch(Buf& bb, const float* __restrict__ xc,
                                        const int roff[4], int offm1, int offp4)
{
#pragma unroll
    for (int r = 0; r < 4; ++r) {
        const float* row = xc + roff[r];
        bb.m[r]  = *(const float4*)row;   // columns w..w+3
        bb.vm[r] = __ldg(row + offm1);    // column w-1
        bb.vp[r] = __ldg(row + offp4);    // column w+4
    }
}

__device__ __forceinline__ void compute_store(const Buf& bb,
                                              const float4 fv0[9], const float4 fv1[9],
                                              float* __restrict__ oc)
{
    // output row h: input rows 0,1,2
    float a0 = 0.f, a1 = 0.f, a2 = 0.f, a3 = 0.f;
#pragma unroll
    for (int j = 0; j < 3; ++j) {
        float4 F0 = fv0[3 * j + 0], F1 = fv0[3 * j + 1], F2 = fv0[3 * j + 2];
        float4 mm = bb.m[j]; float vml = bb.vm[j], vpr = bb.vp[j];
        a0 = fmaf(vml,  F0.x, a0); a0 = fmaf(mm.x, F1.x, a0); a0 = fmaf(mm.y, F2.x, a0);
        a1 = fmaf(mm.x, F0.y, a1); a1 = fmaf(mm.y, F1.y, a1); a1 = fmaf(mm.z, F2.y, a1);
        a2 = fmaf(mm.y, F0.z, a2); a2 = fmaf(mm.z, F1.z, a2); a2 = fmaf(mm.w, F2.z, a2);
        a3 = fmaf(mm.z, F0.w, a3); a3 = fmaf(mm.w, F1.w, a3); a3 = fmaf(vpr,  F2.w, a3);
    }
    // output row h+1: input rows 1,2,3
    float b0 = 0.f, b1 = 0.f, b2 = 0.f, b3 = 0.f;
#pragma unroll
    for (int j = 0; j < 3; ++j) {
        float4 F0 = fv1[3 * j + 0], F1 = fv1[3 * j + 1], F2 = fv1[3 * j + 2];
        float4 mm = bb.m[j + 1]; float vml = bb.vm[j + 1], vpr = bb.vp[j + 1];
        b0 = fmaf(vml,  F0.x, b0); b0 = fmaf(mm.x, F1.x, b0); b0 = fmaf(mm.y, F2.x, b0);
        b1 = fmaf(mm.x, F0.y, b1); b1 = fmaf(mm.y, F1.y, b1); b1 = fmaf(mm.z, F2.y, b1);
        b2 = fmaf(mm.y, F0.z, b2); b2 = fmaf(mm.z, F1.z, b2); b2 = fmaf(mm.w, F2.z, b2);
        b3 = fmaf(mm.z, F0.w, b3); b3 = fmaf(mm.w, F1.w, b3); b3 = fmaf(vpr,  F2.w, b3);
    }
    *(float4*)oc       = make_float4(a0, a1, a2, a3);
    *(float4*)(oc + W) = make_float4(b0, b1, b2, b3);
}

__global__ __launch_bounds__(THREADS, 3)
void duf_kernel(const float* __restrict__ x,
                const float* __restrict__ f,
                float* __restrict__ out)
{
    int idx = blockIdx.x * THREADS + threadIdx.x;

    // consecutive threads -> consecutive wq for coalescing
    int wq = idx % WQ;
    int t  = idx / WQ;
    int hp = t % HP;
    t /= HP;
    int cq = t % NCQ;
    int b  = t / NCQ;
    int w  = wq * 4;
    int h  = hp * 2;                 // output rows h, h+1

    // ---- filter taps for both output rows (pixels w..w+3) ----
    const float* fp0 = f + (size_t)b * 9 * HW + (size_t)h * W + w;
    float4 fv0[9], fv1[9];
#pragma unroll
    for (int i = 0; i < 9; ++i) {
        fv0[i] = *(const float4*)(fp0 + (size_t)i * HW);        // row h
        fv1[i] = *(const float4*)(fp0 + (size_t)i * HW + W);    // row h+1
    }

    // vertical boundaries
    if (hp == 0) {
#pragma unroll
        for (int i = 0; i < 3; ++i) fv0[i] = make_float4(0.f, 0.f, 0.f, 0.f);
    }
    if (hp == HP - 1) {
#pragma unroll
        for (int i = 6; i < 9; ++i) fv1[i] = make_float4(0.f, 0.f, 0.f, 0.f);
    }
    // horizontal boundaries
    if (w == 0) {
        fv0[0].x = 0.f; fv0[3].x = 0.f; fv0[6].x = 0.f;
        fv1[0].x = 0.f; fv1[3].x = 0.f; fv1[6].x = 0.f;
    }
    if (w == W - 4) {
        fv0[2].w = 0.f; fv0[5].w = 0.f; fv0[8].w = 0.f;
        fv1[2].w = 0.f; fv1[5].w = 0.f; fv1[8].w = 0.f;
    }

    // input rows h-1 .. h+2, clamped (dead loads in-bounds, filter zeroed)
    int roff[4];
    roff[0] = (hp > 0)      ? -W    : 0;     // row h-1
    roff[1] = 0;                              // row h
    roff[2] = W;                              // row h+1
    roff[3] = (hp < HP - 1) ? 2 * W : W;     // row h+2
    int offm1 = (w > 0)     ? -1 : 0;        // column w-1
    int offp4 = (w + 4 < W) ?  4 : 3;        // column w+4

    const float* xp = x   + ((size_t)b * C + cq * CCH) * HW + (size_t)h * W + w;
    float*       op = out + ((size_t)b * C + cq * CCH) * HW + (size_t)h * W + w;

    // ---- software-pipelined channel loop (double buffer) ----
    Buf buf0, buf1;
    load_ch(buf0, xp, roff, offm1, offp4);               // c = 0

#pragma unroll
    for (int c = 0; c < CCH; c += 2) {
        // issue loads for c+1, then compute c (independent -> no stall)
        if (c + 1 < CCH)
            load_ch(buf1, xp + (size_t)(c + 1) * HW, roff, offm1, offp4);
        compute_store(buf0, fv0, fv1, op + (size_t)c * HW);

        // issue loads for c+2, then compute c+1
        if (c + 2 < CCH)
            load_ch(buf0, xp + (size_t)(c + 2) * HW, roff, offm1, offp4);
        if (c + 1 < CCH)
            compute_store(buf1, fv0, fv1, op + (size_t)(c + 1) * HW);
    }
}

extern "C" void kernel_launch(void* const* d_in, const int* in_sizes, int n_in,
                              void* d_out, int out_size)
{
    const float* x = (const float*)d_in[0];   // [4,128,180,320]
    const float* f = (const float*)d_in[1];   // [4,9,180,320]
    float* out = (float*)d_out;               // [4,128,180,320]

    duf_kernel<<<GRID, THREADS>>>(x, f, out);
}

// round 10
// speedup vs baseline: 1.1284x; 1.0437x over previous
#include <cuda_runtime.h>

// DynamicUpsamplingFilter: out[b,c,h,w] = sum_{dy,dx} x_pad[b,c,h+dy,w+dx] * filters[b,dy*3+dx,h,w]
// x: [4,128,180,320] f32, filters: [4,9,180,320] f32, out: [4,128,180,320] f32.
//
// R10 = R9 (4w x 2h tile, 16 ch/thread, pipelined; 49.7us) with a deeper,
// skewed pipeline: vector loads (LDG.128) prefetched at distance 2
// (triple buffer), halo loads (LDG.32) at distance 1 (double buffer).
// Live regs ~156 -> still fits launch_bounds(128,3) = 12 warps/SM.
// Channel loop fully unrolled so %3/%2 buffer indices are compile-time.

constexpr int B = 4, C = 128, H = 180, W = 320;
constexpr int HW = H * W;
constexpr int WQ = W / 4;            // 80 pixel-quads per row
constexpr int HP = H / 2;            // 90 row-pairs
constexpr int CCH = 16;              // channels per thread
constexpr int NCQ = C / CCH;         // 8 channel-groups
constexpr int THREADS = 128;
constexpr int NTHREADS_TOTAL = B * NCQ * HP * WQ;  // 230400
constexpr int GRID = NTHREADS_TOTAL / THREADS;     // 1800

__global__ __launch_bounds__(THREADS, 3)
void duf_kernel(const float* __restrict__ x,
                const float* __restrict__ f,
                float* __restrict__ out)
{
    int idx = blockIdx.x * THREADS + threadIdx.x;

    // consecutive threads -> consecutive wq for coalescing
    int wq = idx % WQ;
    int t  = idx / WQ;
    int hp = t % HP;
    t /= HP;
    int cq = t % NCQ;
    int b  = t / NCQ;
    int w  = wq * 4;
    int h  = hp * 2;                 // output rows h, h+1

    // ---- filter taps for both output rows (pixels w..w+3) ----
    const float* fp0 = f + (size_t)b * 9 * HW + (size_t)h * W + w;
    float4 fv0[9], fv1[9];
#pragma unroll
    for (int i = 0; i < 9; ++i) {
        fv0[i] = *(const float4*)(fp0 + (size_t)i * HW);        // row h
        fv1[i] = *(const float4*)(fp0 + (size_t)i * HW + W);    // row h+1
    }

    // vertical boundaries
    if (hp == 0) {
#pragma unroll
        for (int i = 0; i < 3; ++i) fv0[i] = make_float4(0.f, 0.f, 0.f, 0.f);
    }
    if (hp == HP - 1) {
#pragma unroll
        for (int i = 6; i < 9; ++i) fv1[i] = make_float4(0.f, 0.f, 0.f, 0.f);
    }
    // horizontal boundaries
    if (w == 0) {
        fv0[0].x = 0.f; fv0[3].x = 0.f; fv0[6].x = 0.f;
        fv1[0].x = 0.f; fv1[3].x = 0.f; fv1[6].x = 0.f;
    }
    if (w == W - 4) {
        fv0[2].w = 0.f; fv0[5].w = 0.f; fv0[8].w = 0.f;
        fv1[2].w = 0.f; fv1[5].w = 0.f; fv1[8].w = 0.f;
    }

    // input rows h-1 .. h+2, clamped (dead loads in-bounds, filter zeroed)
    int roff[4];
    roff[0] = (hp > 0)      ? -W    : 0;     // row h-1
    roff[1] = 0;                              // row h
    roff[2] = W;                              // row h+1
    roff[3] = (hp < HP - 1) ? 2 * W : W;     // row h+2
    int offm1 = (w > 0)     ? -1 : 0;        // column w-1
    int offp4 = (w + 4 < W) ?  4 : 3;        // column w+4

    const float* xp = x   + ((size_t)b * C + cq * CCH) * HW + (size_t)h * W + w;
    float*       op = out + ((size_t)b * C + cq * CCH) * HW + (size_t)h * W + w;

    // ---- skewed software pipeline ----
    // m (LDG.128): triple buffer, prefetch distance 2
    // vm/vp (LDG.32): double buffer, prefetch distance 1
    float4 mb[3][4];
    float  vmb[2][4], vpb[2][4];

    auto load_m = [&](float4 dst[4], int c) {
        const float* xc = xp + (size_t)c * HW;
#pragma unroll
        for (int r = 0; r < 4; ++r)
            dst[r] = *(const float4*)(xc + roff[r]);
    };
    auto load_halo = [&](float dm[4], float dp[4], int c) {
        const float* xc = xp + (size_t)c * HW;
#pragma unroll
        for (int r = 0; r < 4; ++r) {
            const float* row = xc + roff[r];
            dm[r] = __ldg(row + offm1);
            dp[r] = __ldg(row + offp4);
        }
    };

    // prologue
    load_m(mb[0], 0);
    load_m(mb[1], 1);
    load_halo(vmb[0], vpb[0], 0);

#pragma unroll
    for (int c = 0; c < CCH; ++c) {
        // prefetches first (independent of this iteration's consumers)
        if (c + 2 < CCH) load_m(mb[(c + 2) % 3], c + 2);
        if (c + 1 < CCH) load_halo(vmb[(c + 1) % 2], vpb[(c + 1) % 2], c + 1);

        const float4* m  = mb[c % 3];
        const float*  vm = vmb[c % 2];
        const float*  vp = vpb[c % 2];

        // output row h: input rows 0,1,2
        float a0 = 0.f, a1 = 0.f, a2 = 0.f, a3 = 0.f;
#pragma unroll
        for (int j = 0; j < 3; ++j) {
            float4 F0 = fv0[3 * j + 0], F1 = fv0[3 * j + 1], F2 = fv0[3 * j + 2];
            float4 mm = m[j]; float vml = vm[j], vpr = vp[j];
            a0 = fmaf(vml,  F0.x, a0); a0 = fmaf(mm.x, F1.x, a0); a0 = fmaf(mm.y, F2.x, a0);
            a1 = fmaf(mm.x, F0.y, a1); a1 = fmaf(mm.y, F1.y, a1); a1 = fmaf(mm.z, F2.y, a1);
            a2 = fmaf(mm.y, F0.z, a2); a2 = fmaf(mm.z, F1.z, a2); a2 = fmaf(mm.w, F2.z, a2);
            a3 = fmaf(mm.z, F0.w, a3); a3 = fmaf(mm.w, F1.w, a3); a3 = fmaf(vpr,  F2.w, a3);
        }
        // output row h+1: input rows 1,2,3
        float b0 = 0.f, b1 = 0.f, b2 = 0.f, b3 = 0.f;
#pragma unroll
        for (int j = 0; j < 3; ++j) {
            float4 F0 = fv1[3 * j + 0], F1 = fv1[3 * j + 1], F2 = fv1[3 * j + 2];
            float4 mm = m[j + 1]; float vml = vm[j + 1], vpr = vp[j + 1];
            b0 = fmaf(vml,  F0.x, b0); b0 = fmaf(mm.x, F1.x, b0); b0 = fmaf(mm.y, F2.x, b0);
            b1 = fmaf(mm.x, F0.y, b1); b1 = fmaf(mm.y, F1.y, b1); b1 = fmaf(mm.z, F2.y, b1);
            b2 = fmaf(mm.y, F0.z, b2); b2 = fmaf(mm.z, F1.z, b2); b2 = fmaf(mm.w, F2.z, b2);
            b3 = fmaf(mm.z, F0.w, b3); b3 = fmaf(mm.w, F1.w, b3); b3 = fmaf(vpr,  F2.w, b3);
        }

        float* oc = op + (size_t)c * HW;
        *(float4*)oc       = make_float4(a0, a1, a2, a3);
        *(float4*)(oc + W) = make_float4(b0, b1, b2, b3);
    }
}

extern "C" void kernel_launch(void* const* d_in, const int* in_sizes, int n_in,
                              void* d_out, int out_size)
{
    const float* x = (const float*)d_in[0];   // [4,128,180,320]
    const float* f = (const float*)d_in[1];   // [4,9,180,320]
    float* out = (float*)d_out;               // [4,128,180,320]

    duf_kernel<<<GRID, THREADS>>>(x, f, out);
}